// round 8
// baseline (speedup 1.0000x reference)
#include <cuda_runtime.h>
#include <cstdint>

#define NPOS   16384
#define SCALEF 0.125f

// -------- scratch (device globals; no allocation allowed) --------
__device__ float g_qk[(size_t)NPOS * 2048];    // 134 MB
__device__ float g_ybar[(size_t)NPOS * 2048];  // 134 MB (tf32-rounded)
__device__ float g_q [(size_t)NPOS * 512];     //  33 MB (tf32-rounded)
__device__ float g_v [(size_t)NPOS * 512];     //  33 MB (tf32-rounded)
__device__ float g_xt[(size_t)NPOS * 256];     //  17 MB (x, tf32-rounded)
__device__ float g_wqs [256 * 512];            // SCALE*Wq, tf32   [k=i][n]
__device__ float g_wkT [8 * 64 * 256];         // Wk^T per head    [h][d][c]
__device__ float g_wvT [8 * 256 * 64];         // Wv per head      [h][c][d]
__device__ float g_wouT[512 * 256];            // Wout, tf32       [k][n]

// ================= TF32 helpers =================
__device__ __forceinline__ float f2tf(float x) {
    uint32_t u;
    asm("cvt.rna.tf32.f32 %0, %1;" : "=r"(u) : "f"(x));
    return __uint_as_float(u);
}

__device__ __forceinline__ void mma8(float* d, const uint32_t* a, const uint32_t* b) {
    asm volatile(
        "mma.sync.aligned.m16n8k8.row.col.f32.tf32.tf32.f32 "
        "{%0,%1,%2,%3}, {%4,%5,%6,%7}, {%8,%9}, {%0,%1,%2,%3};"
        : "+f"(d[0]), "+f"(d[1]), "+f"(d[2]), "+f"(d[3])
        : "r"(a[0]), "r"(a[1]), "r"(a[2]), "r"(a[3]), "r"(b[0]), "r"(b[1]));
}

__device__ __forceinline__ void cpasync16(uint32_t s, const void* g) {
    asm volatile("cp.async.cg.shared.global [%0], [%1], 16;" :: "r"(s), "l"(g));
}

// ================= prep kernels (tf32-rounded weight layouts) =================
__global__ __launch_bounds__(256)
void prep_weights(const float* __restrict__ Wq, const float* __restrict__ Wkv,
                  const float* __restrict__ Wout,
                  float* __restrict__ wqs, float* __restrict__ wkT,
                  float* __restrict__ wvT, float* __restrict__ wouT)
{
    int idx = blockIdx.x * 256 + threadIdx.x;
    int sel = idx >> 17;
    int r = idx & 131071;
    if (sel == 0) {
        wqs[r] = f2tf(SCALEF * Wq[r]);                 // [i][n] n-contig
    } else if (sel == 1) {
        int h = r >> 14, d = (r >> 8) & 63, c = r & 255;
        wkT[r] = f2tf(Wkv[c * 1024 + h * 64 + d]);     // [h][d][c]
    } else if (sel == 2) {
        int h = r >> 14, c = (r >> 6) & 255, d = r & 63;
        wvT[r] = f2tf(Wkv[c * 1024 + 512 + h * 64 + d]); // [h][c][d]
    } else {
        wouT[r] = f2tf(Wout[r]);                       // [dd][j] n-contig
    }
}

__global__ __launch_bounds__(256)
void xtf_kernel(const float* __restrict__ in, float* __restrict__ outp)
{
    int i = blockIdx.x * 256 + threadIdx.x;     // per float4
    float4 v = ((const float4*)in)[i];
    v.x = f2tf(v.x); v.y = f2tf(v.y); v.z = f2tf(v.z); v.w = f2tf(v.w);
    ((float4*)outp)[i] = v;
}

// ================= TF32 GEMM (generic, 2-stage cp.async) ====================
#define BM 128
#define BK 32
#define ASTR 36
#define A_FLOATS (BM * ASTR)        // 4608

template<int BNT>
__global__ __launch_bounds__(256, 2)
void gemm4(const float* __restrict__ A, const float* __restrict__ B,
           float* __restrict__ C, const float* __restrict__ bias,
           int K, int lda, int ldb, int ldc,
           long long aB, long long bB, long long cB, int doRound)
{
    constexpr int BSTR = BNT + 8;
    constexpr int B_FLOATS = BK * BSTR;
    constexpr int STAGEF = A_FLOATS + B_FLOATS;
    constexpr int MI = (BNT == 128) ? 4 : 2;
    constexpr int BN4 = BNT / 4;
    constexpr int NB_I = (BK * BN4) / 256;

    extern __shared__ float sm[];

    const int t = threadIdx.x;
    const int lane = t & 31, wid = t >> 5;
    const int g = lane >> 2, tig = lane & 3;
    const int wm = (BNT == 128) ? (wid & 1) * 64 : (wid & 3) * 32;
    const int wn = (BNT == 128) ? (wid >> 1) * 32 : (wid >> 2) * 32;
    const long long bm = (long long)blockIdx.x * BM;
    const long long bn = (long long)blockIdx.y * BNT;

    const float* Ab = A + (long long)blockIdx.z * aB;
    const float* Bb = B + (long long)blockIdx.z * bB + bn;
    float*       Cb = C + (long long)blockIdx.z * cB;

    uint32_t sA[2], sB[2];
#pragma unroll
    for (int s = 0; s < 2; s++) {
        sA[s] = (uint32_t)__cvta_generic_to_shared(sm + s * STAGEF);
        sB[s] = (uint32_t)__cvta_generic_to_shared(sm + s * STAGEF + A_FLOATS);
    }

    float acc[MI][4][4];
#pragma unroll
    for (int i = 0; i < MI; i++)
#pragma unroll
        for (int j = 0; j < 4; j++)
#pragma unroll
            for (int q = 0; q < 4; q++) acc[i][j][q] = 0.f;

    const int ntiles = K / BK;

#pragma unroll
    for (int i = 0; i < 4; i++) {
        int idx = i * 256 + t;
        int r = idx >> 3, c4 = idx & 7;
        cpasync16(sA[0] + (r * ASTR + c4 * 4) * 4, Ab + (bm + r) * lda + c4 * 4);
    }
#pragma unroll
    for (int i = 0; i < NB_I; i++) {
        int idx = i * 256 + t;
        int k = idx / BN4, n4 = idx % BN4;
        cpasync16(sB[0] + (k * BSTR + n4 * 4) * 4, Bb + (long long)k * ldb + n4 * 4);
    }
    asm volatile("cp.async.commit_group;");

    for (int it = 0; it < ntiles; it++) {
        const int buf = it & 1;
        if (it + 1 < ntiles) {
            const int nb = buf ^ 1;
            const long long ko = (long long)(it + 1) * BK;
#pragma unroll
            for (int i = 0; i < 4; i++) {
                int idx = i * 256 + t;
                int r = idx >> 3, c4 = idx & 7;
                cpasync16(sA[nb] + (r * ASTR + c4 * 4) * 4,
                          Ab + (bm + r) * lda + ko + c4 * 4);
            }
#pragma unroll
            for (int i = 0; i < NB_I; i++) {
                int idx = i * 256 + t;
                int k = idx / BN4, n4 = idx % BN4;
                cpasync16(sB[nb] + (k * BSTR + n4 * 4) * 4,
                          Bb + (ko + k) * ldb + n4 * 4);
            }
            asm volatile("cp.async.commit_group;");
            asm volatile("cp.async.wait_group 1;");
        } else {
            asm volatile("cp.async.wait_group 0;");
        }
        __syncthreads();

        const float* as = sm + buf * STAGEF;
        const float* bs = as + A_FLOATS;
#pragma unroll
        for (int ks = 0; ks < 4; ks++) {
            const int k0 = ks * 8;
            uint32_t af[MI][4], bf[4][2];
#pragma unroll
            for (int mi = 0; mi < MI; mi++) {
                const int r = wm + mi * 16 + g;
                af[mi][0] = __float_as_uint(as[r * ASTR + k0 + tig]);
                af[mi][1] = __float_as_uint(as[(r + 8) * ASTR + k0 + tig]);
                af[mi][2] = __float_as_uint(as[r * ASTR + k0 + tig + 4]);
                af[mi][3] = __float_as_uint(as[(r + 8) * ASTR + k0 + tig + 4]);
            }
#pragma unroll
            for (int ni = 0; ni < 4; ni++) {
                const int cn = wn + ni * 8 + g;
                bf[ni][0] = __float_as_uint(bs[(k0 + tig) * BSTR + cn]);
                bf[ni][1] = __float_as_uint(bs[(k0 + tig + 4) * BSTR + cn]);
            }
#pragma unroll
            for (int mi = 0; mi < MI; mi++)
#pragma unroll
                for (int ni = 0; ni < 4; ni++)
                    mma8(acc[mi][ni], af[mi], bf[ni]);
        }
        __syncthreads();
    }

#pragma unroll
    for (int mi = 0; mi < MI; mi++) {
#pragma unroll
        for (int ni = 0; ni < 4; ni++) {
            const long long r = bm + wm + mi * 16 + g;
            const int cn = (int)bn + wn + ni * 8 + 2 * tig;
            float v0 = acc[mi][ni][0], v1 = acc[mi][ni][1];
            float v2 = acc[mi][ni][2], v3 = acc[mi][ni][3];
            if (bias) {
                float b0 = bias[cn], b1 = bias[cn + 1];
                v0 += b0; v1 += b1; v2 += b0; v3 += b1;
            }
            if (doRound) {
                v0 = f2tf(v0); v1 = f2tf(v1); v2 = f2tf(v2); v3 = f2tf(v3);
            }
            *(float2*)(Cb + r * ldc + cn)       = make_float2(v0, v1);
            *(float2*)(Cb + (r + 8) * ldc + cn) = make_float2(v2, v3);
        }
    }
}

// ================= weight-stationary GEMM for K=64 (G2) ======================
// Per CTA: load full B panel (64 x 128) once; loop MT m-tiles of 128 rows with
// double-buffered A. C[m,n] = sum_k A[m,k]*B[k,n]. No bias, no rounding.
#define WS_ASTR 68                   // 64 + 4
#define WS_BSTR 136                  // 128 + 8
#define WS_STAGEF (128 * WS_ASTR)    // 8704 floats per A stage
#define WS_BFLOATS (64 * WS_BSTR)    // 8704 floats
#define WS_SMEM ((WS_BFLOATS + 2 * WS_STAGEF) * 4)   // 104448 bytes

template<int MT>
__global__ __launch_bounds__(256, 2)
void gemm_ws(const float* __restrict__ A, const float* __restrict__ B,
             float* __restrict__ C,
             int lda, int ldb, int ldc,
             long long aB, long long bB, long long cB)
{
    extern __shared__ float sm[];
    float* Bs = sm;                       // [64][136]
    float* As = sm + WS_BFLOATS;          // [2][128][68]

    const int t = threadIdx.x;
    const int lane = t & 31, wid = t >> 5;
    const int g = lane >> 2, tig = lane & 3;
    const int wm = (wid & 1) * 64;
    const int wn = (wid >> 1) * 32;
    const long long bm0 = (long long)blockIdx.x * (128 * MT);
    const long long bn  = (long long)blockIdx.y * 128;

    const float* Ab = A + (long long)blockIdx.z * aB;
    const float* Bb = B + (long long)blockIdx.z * bB + bn;
    float*       Cb = C + (long long)blockIdx.z * cB;

    uint32_t sBs = (uint32_t)__cvta_generic_to_shared(Bs);
    uint32_t sAs[2];
    sAs[0] = (uint32_t)__cvta_generic_to_shared(As);
    sAs[1] = (uint32_t)__cvta_generic_to_shared(As + WS_STAGEF);

    // load B: 64 rows x 128 floats = 2048 float4 chunks / 256 thr = 8 each
#pragma unroll
    for (int i = 0; i < 8; i++) {
        int idx = i * 256 + t;
        int k = idx >> 5, n4 = idx & 31;
        cpasync16(sBs + (k * WS_BSTR + n4 * 4) * 4, Bb + (long long)k * ldb + n4 * 4);
    }
    asm volatile("cp.async.commit_group;");

    // load A tile: 128 rows x 64 floats = 2048 chunks / 256 thr = 8 each
    auto load_a = [&](int st, long long row0) {
#pragma unroll
        for (int i = 0; i < 8; i++) {
            int idx = i * 256 + t;
            int r = idx >> 4, c4 = idx & 15;
            cpasync16(sAs[st] + (r * WS_ASTR + c4 * 4) * 4,
                      Ab + (row0 + r) * lda + c4 * 4);
        }
        asm volatile("cp.async.commit_group;");
    };

    load_a(0, bm0);

    for (int mt = 0; mt < MT; mt++) {
        const int buf = mt & 1;
        if (mt + 1 < MT) {
            load_a(buf ^ 1, bm0 + (long long)(mt + 1) * 128);
            asm volatile("cp.async.wait_group 1;");
        } else {
            asm volatile("cp.async.wait_group 0;");
        }
        __syncthreads();

        float acc[4][4][4];
#pragma unroll
        for (int i = 0; i < 4; i++)
#pragma unroll
            for (int j = 0; j < 4; j++)
#pragma unroll
                for (int q = 0; q < 4; q++) acc[i][j][q] = 0.f;

        const float* as = As + buf * WS_STAGEF;
#pragma unroll
        for (int ks = 0; ks < 8; ks++) {
            const int k0 = ks * 8;
            uint32_t af[4][4], bf[4][2];
#pragma unroll
            for (int mi = 0; mi < 4; mi++) {
                const int r = wm + mi * 16 + g;
                af[mi][0] = __float_as_uint(as[r * WS_ASTR + k0 + tig]);
                af[mi][1] = __float_as_uint(as[(r + 8) * WS_ASTR + k0 + tig]);
                af[mi][2] = __float_as_uint(as[r * WS_ASTR + k0 + tig + 4]);
                af[mi][3] = __float_as_uint(as[(r + 8) * WS_ASTR + k0 + tig + 4]);
            }
#pragma unroll
            for (int ni = 0; ni < 4; ni++) {
                const int cn = wn + ni * 8 + g;
                bf[ni][0] = __float_as_uint(Bs[(k0 + tig) * WS_BSTR + cn]);
                bf[ni][1] = __float_as_uint(Bs[(k0 + tig + 4) * WS_BSTR + cn]);
            }
#pragma unroll
            for (int mi = 0; mi < 4; mi++)
#pragma unroll
                for (int ni = 0; ni < 4; ni++)
                    mma8(acc[mi][ni], af[mi], bf[ni]);
        }

        // epilogue for this m-tile
#pragma unroll
        for (int mi = 0; mi < 4; mi++) {
#pragma unroll
            for (int ni = 0; ni < 4; ni++) {
                const long long r = bm0 + (long long)mt * 128 + wm + mi * 16 + g;
                const int cn = (int)bn + wn + ni * 8 + 2 * tig;
                *(float2*)(Cb + r * ldc + cn) =
                    make_float2(acc[mi][ni][0], acc[mi][ni][1]);
                *(float2*)(Cb + (r + 8) * ldc + cn) =
                    make_float2(acc[mi][ni][2], acc[mi][ni][3]);
            }
        }
        __syncthreads();   // protect As[buf] before it is reloaded in iter mt+2
    }
}

// ================= fused attention core: tensor-core dots =================
#define YP 260

__global__ __launch_bounds__(128)
void attn3(const float* __restrict__ y, const float* __restrict__ qk,
           float* __restrict__ ybar)
{
    __shared__ float ys[16 * YP];
    __shared__ float qs[8 * YP];
    __shared__ float part[4][128];
    __shared__ float attn_s[128];

    const int p = blockIdx.x;
    const int t = threadIdx.x;
    const float* yg = y  + (long long)p * 4096;
    const float* qg = qk + (long long)p * 2048;

#pragma unroll
    for (int i = 0; i < 8; i++) {
        int idx4 = i * 128 + t;
        float4 v = *(const float4*)(yg + idx4 * 4);
        int m = idx4 >> 6, c = (idx4 & 63) * 4;
        *(float4*)(ys + m * YP + c) = v;
    }
#pragma unroll
    for (int i = 0; i < 4; i++) {
        int idx4 = i * 128 + t;
        float4 v = *(const float4*)(qg + idx4 * 4);
        int h = idx4 >> 6, c = (idx4 & 63) * 4;
        *(float4*)(qs + h * YP + c) = v;
    }
    __syncthreads();

    const int lane = t & 31, w = t >> 5;
    const int g = lane >> 2, tig = lane & 3;

    float acc[4] = {0.f, 0.f, 0.f, 0.f};
#pragma unroll
    for (int cc = 0; cc < 8; cc++) {
        const int c0 = w * 64 + cc * 8;
        float a[4], b[2];
        a[0] = ys[g * YP + c0 + tig];
        a[1] = ys[(g + 8) * YP + c0 + tig];
        a[2] = ys[g * YP + c0 + tig + 4];
        a[3] = ys[(g + 8) * YP + c0 + tig + 4];
        b[0] = qs[g * YP + c0 + tig];
        b[1] = qs[g * YP + c0 + tig + 4];

        uint32_t ah[4], al[4], bh[2], bl[2];
#pragma unroll
        for (int i = 0; i < 4; i++) {
            float hi = f2tf(a[i]);
            ah[i] = __float_as_uint(hi);
            al[i] = __float_as_uint(f2tf(a[i] - hi));
        }
#pragma unroll
        for (int i = 0; i < 2; i++) {
            float hi = f2tf(b[i]);
            bh[i] = __float_as_uint(hi);
            bl[i] = __float_as_uint(f2tf(b[i] - hi));
        }
        mma8(acc, ah, bh);
        mma8(acc, al, bh);
        mma8(acc, ah, bl);
    }
    part[w][g * 8 + 2 * tig]           = acc[0];
    part[w][g * 8 + 2 * tig + 1]       = acc[1];
    part[w][(g + 8) * 8 + 2 * tig]     = acc[2];
    part[w][(g + 8) * 8 + 2 * tig + 1] = acc[3];
    __syncthreads();

    const int h = t >> 4, m = t & 15;
    float dot = part[0][m * 8 + h] + part[1][m * 8 + h]
              + part[2][m * 8 + h] + part[3][m * 8 + h];

    float mx = dot;
#pragma unroll
    for (int o = 8; o >= 1; o >>= 1)
        mx = fmaxf(mx, __shfl_xor_sync(0xffffffffu, mx, o));
    float e = __expf(dot - mx);
    float s = e;
#pragma unroll
    for (int o = 8; o >= 1; o >>= 1)
        s += __shfl_xor_sync(0xffffffffu, s, o);
    attn_s[m * 8 + h] = e / s;
    __syncthreads();

    const int c0 = 2 * t;
    float2 acc2[8];
#pragma unroll
    for (int i = 0; i < 8; i++) acc2[i] = make_float2(0.f, 0.f);

#pragma unroll
    for (int mm = 0; mm < 16; mm++) {
        float4 a0 = *(const float4*)(attn_s + mm * 8);
        float4 a1 = *(const float4*)(attn_s + mm * 8 + 4);
        float2 yv = *(const float2*)(ys + mm * YP + c0);
        acc2[0].x = fmaf(a0.x, yv.x, acc2[0].x); acc2[0].y = fmaf(a0.x, yv.y, acc2[0].y);
        acc2[1].x = fmaf(a0.y, yv.x, acc2[1].x); acc2[1].y = fmaf(a0.y, yv.y, acc2[1].y);
        acc2[2].x = fmaf(a0.z, yv.x, acc2[2].x); acc2[2].y = fmaf(a0.z, yv.y, acc2[2].y);
        acc2[3].x = fmaf(a0.w, yv.x, acc2[3].x); acc2[3].y = fmaf(a0.w, yv.y, acc2[3].y);
        acc2[4].x = fmaf(a1.x, yv.x, acc2[4].x); acc2[4].y = fmaf(a1.x, yv.y, acc2[4].y);
        acc2[5].x = fmaf(a1.y, yv.x, acc2[5].x); acc2[5].y = fmaf(a1.y, yv.y, acc2[5].y);
        acc2[6].x = fmaf(a1.z, yv.x, acc2[6].x); acc2[6].y = fmaf(a1.z, yv.y, acc2[6].y);
        acc2[7].x = fmaf(a1.w, yv.x, acc2[7].x); acc2[7].y = fmaf(a1.w, yv.y, acc2[7].y);
    }

    // write ybar pre-rounded to tf32 (v-proj consumes it directly)
    float* op = ybar + (long long)p * 2048 + c0;
#pragma unroll
    for (int hh = 0; hh < 8; hh++) {
        float2 v = make_float2(f2tf(acc2[hh].x), f2tf(acc2[hh].y));
        *(float2*)(op + hh * 256) = v;
    }
}

// ================= launch =================
extern "C" void kernel_launch(void* const* d_in, const int* in_sizes, int n_in,
                              void* d_out, int out_size)
{
    const float* x     = (const float*)d_in[0];
    const float* y     = (const float*)d_in[1];
    const float* W_q   = (const float*)d_in[2];
    const float* W_kv  = (const float*)d_in[3];
    const float* W_out = (const float*)d_in[4];
    const float* b_out = (const float*)d_in[5];
    float* out = (float*)d_out;

    float *qk, *ybar, *q, *v, *xt, *wqs, *wkT, *wvT, *wouT;
    cudaGetSymbolAddress((void**)&qk,   g_qk);
    cudaGetSymbolAddress((void**)&ybar, g_ybar);
    cudaGetSymbolAddress((void**)&q,    g_q);
    cudaGetSymbolAddress((void**)&v,    g_v);
    cudaGetSymbolAddress((void**)&xt,   g_xt);
    cudaGetSymbolAddress((void**)&wqs,  g_wqs);
    cudaGetSymbolAddress((void**)&wkT,  g_wkT);
    cudaGetSymbolAddress((void**)&wvT,  g_wvT);
    cudaGetSymbolAddress((void**)&wouT, g_wouT);

    const int SM128 = 2 * (A_FLOATS + BK * (128 + 8)) * 4;   // 71680
    const int SM64  = 2 * (A_FLOATS + BK * (64 + 8)) * 4;    // 55296
    cudaFuncSetAttribute(gemm4<128>, cudaFuncAttributeMaxDynamicSharedMemorySize, SM128);
    cudaFuncSetAttribute(gemm4<64>,  cudaFuncAttributeMaxDynamicSharedMemorySize, SM64);
    cudaFuncSetAttribute(gemm_ws<4>, cudaFuncAttributeMaxDynamicSharedMemorySize, WS_SMEM);

    // P0: weight layouts + round x
    prep_weights<<<2048, 256>>>(W_q, W_kv, W_out, wqs, wkT, wvT, wouT);
    xtf_kernel<<<4096, 256>>>(x, xt);

    // G1: q = xt @ wqs         (M=16384, N=512, K=256), round out
    gemm4<128><<<dim3(128, 4, 1), 256, SM128>>>(xt, wqs, q, nullptr,
                                                256, 256, 512, 512, 0, 0, 0, 1);

    // G2: qk_h = q_h @ Wk_h^T  (per head: M=16384, N=256, K=64) — weight-stationary
    gemm_ws<4><<<dim3(32, 2, 8), 256, WS_SMEM>>>(q, wkT, qk,
                                                 512, 256, 2048,
                                                 64, 16384, 256);

    // K_B: dots -> softmax -> ybar (tf32-rounded)
    attn3<<<NPOS, 128>>>(y, qk, ybar);

    // G3: v_h = ybar_h @ Wv_h  (per head: M=16384, N=64, K=256), round out
    gemm4<64><<<dim3(128, 1, 8), 256, SM64>>>(ybar, wvT, v, nullptr,
                                              256, 2048, 64, 512,
                                              256, 16384, 64, 1);

    // G4: out = v @ wouT + b_out  (M=16384, N=256, K=512), 512 CTAs for balance
    gemm4<64><<<dim3(128, 4, 1), 256, SM64>>>(v, wouT, out, b_out,
                                              512, 512, 256, 256, 0, 0, 0, 0);
}

// round 9
// speedup vs baseline: 1.1244x; 1.1244x over previous
#include <cuda_runtime.h>
#include <cstdint>

#define NPOS   16384
#define SCALEF 0.125f

// -------- scratch (device globals; no allocation allowed) --------
__device__ float g_qk[(size_t)NPOS * 2048];    // 134 MB
__device__ float g_ybar[(size_t)NPOS * 2048];  // 134 MB (tf32-rounded)
__device__ float g_q [(size_t)NPOS * 512];     //  33 MB (tf32-rounded)
__device__ float g_v [(size_t)NPOS * 512];     //  33 MB (tf32-rounded)
__device__ float g_xt[(size_t)NPOS * 256];     //  17 MB (x, tf32-rounded)
__device__ float g_wqs [256 * 512];            // SCALE*Wq, tf32   [k=i][n]
__device__ float g_wkT [8 * 64 * 256];         // Wk^T per head    [h][d][c]
__device__ float g_wvT [8 * 256 * 64];         // Wv per head      [h][c][d]
__device__ float g_wouT[512 * 256];            // Wout, tf32       [k][n]

// ================= TF32 helpers =================
__device__ __forceinline__ float f2tf(float x) {
    uint32_t u;
    asm("cvt.rna.tf32.f32 %0, %1;" : "=r"(u) : "f"(x));
    return __uint_as_float(u);
}

__device__ __forceinline__ void mma8(float* d, const uint32_t* a, const uint32_t* b) {
    asm volatile(
        "mma.sync.aligned.m16n8k8.row.col.f32.tf32.tf32.f32 "
        "{%0,%1,%2,%3}, {%4,%5,%6,%7}, {%8,%9}, {%0,%1,%2,%3};"
        : "+f"(d[0]), "+f"(d[1]), "+f"(d[2]), "+f"(d[3])
        : "r"(a[0]), "r"(a[1]), "r"(a[2]), "r"(a[3]), "r"(b[0]), "r"(b[1]));
}

__device__ __forceinline__ void cpasync16(uint32_t s, const void* g) {
    asm volatile("cp.async.cg.shared.global [%0], [%1], 16;" :: "r"(s), "l"(g));
}

// ================= prep kernels (tf32-rounded weight layouts) =================
__global__ __launch_bounds__(256)
void prep_weights(const float* __restrict__ Wq, const float* __restrict__ Wkv,
                  const float* __restrict__ Wout,
                  float* __restrict__ wqs, float* __restrict__ wkT,
                  float* __restrict__ wvT, float* __restrict__ wouT)
{
    int idx = blockIdx.x * 256 + threadIdx.x;
    int sel = idx >> 17;
    int r = idx & 131071;
    if (sel == 0) {
        wqs[r] = f2tf(SCALEF * Wq[r]);                 // [i][n] n-contig
    } else if (sel == 1) {
        int h = r >> 14, d = (r >> 8) & 63, c = r & 255;
        wkT[r] = f2tf(Wkv[c * 1024 + h * 64 + d]);     // [h][d][c]
    } else if (sel == 2) {
        int h = r >> 14, c = (r >> 6) & 255, d = r & 63;
        wvT[r] = f2tf(Wkv[c * 1024 + 512 + h * 64 + d]); // [h][c][d]
    } else {
        wouT[r] = f2tf(Wout[r]);                       // [dd][j] n-contig
    }
}

__global__ __launch_bounds__(256)
void xtf_kernel(const float* __restrict__ in, float* __restrict__ outp)
{
    int i = blockIdx.x * 256 + threadIdx.x;     // per float4
    float4 v = ((const float4*)in)[i];
    v.x = f2tf(v.x); v.y = f2tf(v.y); v.z = f2tf(v.z); v.w = f2tf(v.w);
    ((float4*)outp)[i] = v;
}

// ================= TF32 GEMM (generic, 2-stage cp.async) ====================
#define BM 128
#define BK 32
#define ASTR 36
#define A_FLOATS (BM * ASTR)        // 4608

template<int BNT>
__global__ __launch_bounds__(256, 2)
void gemm4(const float* __restrict__ A, const float* __restrict__ B,
           float* __restrict__ C, const float* __restrict__ bias,
           int K, int lda, int ldb, int ldc,
           long long aB, long long bB, long long cB, int doRound)
{
    constexpr int BSTR = BNT + 8;
    constexpr int B_FLOATS = BK * BSTR;
    constexpr int STAGEF = A_FLOATS + B_FLOATS;
    constexpr int MI = (BNT == 128) ? 4 : 2;
    constexpr int BN4 = BNT / 4;
    constexpr int NB_I = (BK * BN4) / 256;

    extern __shared__ float sm[];

    const int t = threadIdx.x;
    const int lane = t & 31, wid = t >> 5;
    const int g = lane >> 2, tig = lane & 3;
    const int wm = (BNT == 128) ? (wid & 1) * 64 : (wid & 3) * 32;
    const int wn = (BNT == 128) ? (wid >> 1) * 32 : (wid >> 2) * 32;
    const long long bm = (long long)blockIdx.x * BM;
    const long long bn = (long long)blockIdx.y * BNT;

    const float* Ab = A + (long long)blockIdx.z * aB;
    const float* Bb = B + (long long)blockIdx.z * bB + bn;
    float*       Cb = C + (long long)blockIdx.z * cB;

    uint32_t sA[2], sB[2];
#pragma unroll
    for (int s = 0; s < 2; s++) {
        sA[s] = (uint32_t)__cvta_generic_to_shared(sm + s * STAGEF);
        sB[s] = (uint32_t)__cvta_generic_to_shared(sm + s * STAGEF + A_FLOATS);
    }

    float acc[MI][4][4];
#pragma unroll
    for (int i = 0; i < MI; i++)
#pragma unroll
        for (int j = 0; j < 4; j++)
#pragma unroll
            for (int q = 0; q < 4; q++) acc[i][j][q] = 0.f;

    const int ntiles = K / BK;

#pragma unroll
    for (int i = 0; i < 4; i++) {
        int idx = i * 256 + t;
        int r = idx >> 3, c4 = idx & 7;
        cpasync16(sA[0] + (r * ASTR + c4 * 4) * 4, Ab + (bm + r) * lda + c4 * 4);
    }
#pragma unroll
    for (int i = 0; i < NB_I; i++) {
        int idx = i * 256 + t;
        int k = idx / BN4, n4 = idx % BN4;
        cpasync16(sB[0] + (k * BSTR + n4 * 4) * 4, Bb + (long long)k * ldb + n4 * 4);
    }
    asm volatile("cp.async.commit_group;");

    for (int it = 0; it < ntiles; it++) {
        const int buf = it & 1;
        if (it + 1 < ntiles) {
            const int nb = buf ^ 1;
            const long long ko = (long long)(it + 1) * BK;
#pragma unroll
            for (int i = 0; i < 4; i++) {
                int idx = i * 256 + t;
                int r = idx >> 3, c4 = idx & 7;
                cpasync16(sA[nb] + (r * ASTR + c4 * 4) * 4,
                          Ab + (bm + r) * lda + ko + c4 * 4);
            }
#pragma unroll
            for (int i = 0; i < NB_I; i++) {
                int idx = i * 256 + t;
                int k = idx / BN4, n4 = idx % BN4;
                cpasync16(sB[nb] + (k * BSTR + n4 * 4) * 4,
                          Bb + (ko + k) * ldb + n4 * 4);
            }
            asm volatile("cp.async.commit_group;");
            asm volatile("cp.async.wait_group 1;");
        } else {
            asm volatile("cp.async.wait_group 0;");
        }
        __syncthreads();

        const float* as = sm + buf * STAGEF;
        const float* bs = as + A_FLOATS;
#pragma unroll
        for (int ks = 0; ks < 4; ks++) {
            const int k0 = ks * 8;
            uint32_t af[MI][4], bf[4][2];
#pragma unroll
            for (int mi = 0; mi < MI; mi++) {
                const int r = wm + mi * 16 + g;
                af[mi][0] = __float_as_uint(as[r * ASTR + k0 + tig]);
                af[mi][1] = __float_as_uint(as[(r + 8) * ASTR + k0 + tig]);
                af[mi][2] = __float_as_uint(as[r * ASTR + k0 + tig + 4]);
                af[mi][3] = __float_as_uint(as[(r + 8) * ASTR + k0 + tig + 4]);
            }
#pragma unroll
            for (int ni = 0; ni < 4; ni++) {
                const int cn = wn + ni * 8 + g;
                bf[ni][0] = __float_as_uint(bs[(k0 + tig) * BSTR + cn]);
                bf[ni][1] = __float_as_uint(bs[(k0 + tig + 4) * BSTR + cn]);
            }
#pragma unroll
            for (int mi = 0; mi < MI; mi++)
#pragma unroll
                for (int ni = 0; ni < 4; ni++)
                    mma8(acc[mi][ni], af[mi], bf[ni]);
        }
        __syncthreads();
    }

#pragma unroll
    for (int mi = 0; mi < MI; mi++) {
#pragma unroll
        for (int ni = 0; ni < 4; ni++) {
            const long long r = bm + wm + mi * 16 + g;
            const int cn = (int)bn + wn + ni * 8 + 2 * tig;
            float v0 = acc[mi][ni][0], v1 = acc[mi][ni][1];
            float v2 = acc[mi][ni][2], v3 = acc[mi][ni][3];
            if (bias) {
                float b0 = bias[cn], b1 = bias[cn + 1];
                v0 += b0; v1 += b1; v2 += b0; v3 += b1;
            }
            if (doRound) {
                v0 = f2tf(v0); v1 = f2tf(v1); v2 = f2tf(v2); v3 = f2tf(v3);
            }
            *(float2*)(Cb + r * ldc + cn)       = make_float2(v0, v1);
            *(float2*)(Cb + (r + 8) * ldc + cn) = make_float2(v2, v3);
        }
    }
}

// ================= fused attention v5: 2 positions per CTA ====================
// slab s = threadIdx.x>>7 handles position p = 2*blockIdx.x + s with 128 threads.
// cp.async staging; split-TF32 mma dots; fp32 softmax/ybar; tf32-rounded output.
#define YP 260
#define YS_F (16 * YP)          // 4160 floats per slab
#define QS_F (8 * YP)           // 2080 floats per slab
#define ATTN_SMEM ((2 * YS_F + 2 * QS_F + 2 * 512 + 2 * 128) * 4)   // 55040 B

__global__ __launch_bounds__(256)
void attn5(const float* __restrict__ y, const float* __restrict__ qk,
           float* __restrict__ ybar)
{
    extern __shared__ float smb[];
    const int s  = threadIdx.x >> 7;     // slab 0/1
    const int t  = threadIdx.x & 127;    // thread within slab

    float* ys     = smb + s * YS_F;
    float* qs     = smb + 2 * YS_F + s * QS_F;
    float* part   = smb + 2 * YS_F + 2 * QS_F + s * 512;     // [4][128]
    float* attn_s = smb + 2 * YS_F + 2 * QS_F + 2 * 512 + s * 128;

    const long long p = (long long)blockIdx.x * 2 + s;
    const float* yg = y  + p * 4096;
    const float* qg = qk + p * 2048;

    // stage y (16x256) and qk (8x256) via cp.async
#pragma unroll
    for (int i = 0; i < 8; i++) {
        int idx4 = i * 128 + t;
        int m = idx4 >> 6, c = (idx4 & 63) * 4;
        cpasync16((uint32_t)__cvta_generic_to_shared(ys + m * YP + c), yg + idx4 * 4);
    }
#pragma unroll
    for (int i = 0; i < 4; i++) {
        int idx4 = i * 128 + t;
        int h = idx4 >> 6, c = (idx4 & 63) * 4;
        cpasync16((uint32_t)__cvta_generic_to_shared(qs + h * YP + c), qg + idx4 * 4);
    }
    asm volatile("cp.async.commit_group;");
    asm volatile("cp.async.wait_group 0;");
    __syncthreads();

    const int lane = t & 31, w = t >> 5;     // warp-in-slab 0..3 (warps don't straddle slabs)
    const int g = lane >> 2, tig = lane & 3;

    // --- dots via split-TF32 mma: warp w covers c in [64w, 64w+64) ---
    float acc[4] = {0.f, 0.f, 0.f, 0.f};
#pragma unroll
    for (int cc = 0; cc < 8; cc++) {
        const int c0 = w * 64 + cc * 8;
        float a[4], b[2];
        a[0] = ys[g * YP + c0 + tig];
        a[1] = ys[(g + 8) * YP + c0 + tig];
        a[2] = ys[g * YP + c0 + tig + 4];
        a[3] = ys[(g + 8) * YP + c0 + tig + 4];
        b[0] = qs[g * YP + c0 + tig];
        b[1] = qs[g * YP + c0 + tig + 4];

        uint32_t ah[4], al[4], bh[2], bl[2];
#pragma unroll
        for (int i = 0; i < 4; i++) {
            float hi = f2tf(a[i]);
            ah[i] = __float_as_uint(hi);
            al[i] = __float_as_uint(f2tf(a[i] - hi));
        }
#pragma unroll
        for (int i = 0; i < 2; i++) {
            float hi = f2tf(b[i]);
            bh[i] = __float_as_uint(hi);
            bl[i] = __float_as_uint(f2tf(b[i] - hi));
        }
        mma8(acc, ah, bh);
        mma8(acc, al, bh);
        mma8(acc, ah, bl);
    }
    part[w * 128 + g * 8 + 2 * tig]           = acc[0];
    part[w * 128 + g * 8 + 2 * tig + 1]       = acc[1];
    part[w * 128 + (g + 8) * 8 + 2 * tig]     = acc[2];
    part[w * 128 + (g + 8) * 8 + 2 * tig + 1] = acc[3];
    __syncthreads();

    const int h = t >> 4, m = t & 15;
    float dot = part[0 * 128 + m * 8 + h] + part[1 * 128 + m * 8 + h]
              + part[2 * 128 + m * 8 + h] + part[3 * 128 + m * 8 + h];

    // softmax over the 16 lanes sharing h (contiguous lanes within warp)
    float mx = dot;
#pragma unroll
    for (int o = 8; o >= 1; o >>= 1)
        mx = fmaxf(mx, __shfl_xor_sync(0xffffffffu, mx, o));
    float e = __expf(dot - mx);
    float sum = e;
#pragma unroll
    for (int o = 8; o >= 1; o >>= 1)
        sum += __shfl_xor_sync(0xffffffffu, sum, o);
    attn_s[m * 8 + h] = e / sum;
    __syncthreads();

    // --- ybar: thread owns 2 c-columns across all 8 heads; y read once ---
    const int c0 = 2 * t;
    float2 acc2[8];
#pragma unroll
    for (int i = 0; i < 8; i++) acc2[i] = make_float2(0.f, 0.f);

#pragma unroll
    for (int mm = 0; mm < 16; mm++) {
        float4 a0 = *(const float4*)(attn_s + mm * 8);
        float4 a1 = *(const float4*)(attn_s + mm * 8 + 4);
        float2 yv = *(const float2*)(ys + mm * YP + c0);
        acc2[0].x = fmaf(a0.x, yv.x, acc2[0].x); acc2[0].y = fmaf(a0.x, yv.y, acc2[0].y);
        acc2[1].x = fmaf(a0.y, yv.x, acc2[1].x); acc2[1].y = fmaf(a0.y, yv.y, acc2[1].y);
        acc2[2].x = fmaf(a0.z, yv.x, acc2[2].x); acc2[2].y = fmaf(a0.z, yv.y, acc2[2].y);
        acc2[3].x = fmaf(a0.w, yv.x, acc2[3].x); acc2[3].y = fmaf(a0.w, yv.y, acc2[3].y);
        acc2[4].x = fmaf(a1.x, yv.x, acc2[4].x); acc2[4].y = fmaf(a1.x, yv.y, acc2[4].y);
        acc2[5].x = fmaf(a1.y, yv.x, acc2[5].x); acc2[5].y = fmaf(a1.y, yv.y, acc2[5].y);
        acc2[6].x = fmaf(a1.z, yv.x, acc2[6].x); acc2[6].y = fmaf(a1.z, yv.y, acc2[6].y);
        acc2[7].x = fmaf(a1.w, yv.x, acc2[7].x); acc2[7].y = fmaf(a1.w, yv.y, acc2[7].y);
    }

    // write ybar pre-rounded to tf32 (v-proj consumes it directly)
    float* op = ybar + p * 2048 + c0;
#pragma unroll
    for (int hh = 0; hh < 8; hh++) {
        float2 v = make_float2(f2tf(acc2[hh].x), f2tf(acc2[hh].y));
        *(float2*)(op + hh * 256) = v;
    }
}

// ================= launch =================
extern "C" void kernel_launch(void* const* d_in, const int* in_sizes, int n_in,
                              void* d_out, int out_size)
{
    const float* x     = (const float*)d_in[0];
    const float* y     = (const float*)d_in[1];
    const float* W_q   = (const float*)d_in[2];
    const float* W_kv  = (const float*)d_in[3];
    const float* W_out = (const float*)d_in[4];
    const float* b_out = (const float*)d_in[5];
    float* out = (float*)d_out;

    float *qk, *ybar, *q, *v, *xt, *wqs, *wkT, *wvT, *wouT;
    cudaGetSymbolAddress((void**)&qk,   g_qk);
    cudaGetSymbolAddress((void**)&ybar, g_ybar);
    cudaGetSymbolAddress((void**)&q,    g_q);
    cudaGetSymbolAddress((void**)&v,    g_v);
    cudaGetSymbolAddress((void**)&xt,   g_xt);
    cudaGetSymbolAddress((void**)&wqs,  g_wqs);
    cudaGetSymbolAddress((void**)&wkT,  g_wkT);
    cudaGetSymbolAddress((void**)&wvT,  g_wvT);
    cudaGetSymbolAddress((void**)&wouT, g_wouT);

    const int SM128 = 2 * (A_FLOATS + BK * (128 + 8)) * 4;   // 71680
    const int SM64  = 2 * (A_FLOATS + BK * (64 + 8)) * 4;    // 55296
    cudaFuncSetAttribute(gemm4<128>, cudaFuncAttributeMaxDynamicSharedMemorySize, SM128);
    cudaFuncSetAttribute(gemm4<64>,  cudaFuncAttributeMaxDynamicSharedMemorySize, SM64);
    cudaFuncSetAttribute(attn5, cudaFuncAttributeMaxDynamicSharedMemorySize, ATTN_SMEM);

    // P0: weight layouts + round x
    prep_weights<<<2048, 256>>>(W_q, W_kv, W_out, wqs, wkT, wvT, wouT);
    xtf_kernel<<<4096, 256>>>(x, xt);

    // G1: q = xt @ wqs         (M=16384, N=512, K=256), round out
    gemm4<128><<<dim3(128, 4, 1), 256, SM128>>>(xt, wqs, q, nullptr,
                                                256, 256, 512, 512, 0, 0, 0, 1);

    // G2: qk_h = q_h @ Wk_h^T  (per head: M=16384, N=256, K=64)
    gemm4<128><<<dim3(128, 2, 8), 256, SM128>>>(q, wkT, qk, nullptr,
                                                64, 512, 256, 2048,
                                                64, 16384, 256, 0);

    // K_B: dots -> softmax -> ybar (tf32-rounded), 2 positions per CTA
    attn5<<<NPOS / 2, 256, ATTN_SMEM>>>(y, qk, ybar);

    // G3: v_h = ybar_h @ Wv_h  (per head: M=16384, N=64, K=256), round out
    gemm4<64><<<dim3(128, 1, 8), 256, SM64>>>(ybar, wvT, v, nullptr,
                                              256, 2048, 64, 512,
                                              256, 16384, 64, 1);

    // G4: out = v @ wouT + b_out  (M=16384, N=256, K=512)
    gemm4<128><<<dim3(128, 2, 1), 256, SM128>>>(v, wouT, out, b_out,
                                                512, 512, 256, 256, 0, 0, 0, 0);
}